// round 14
// baseline (speedup 1.0000x reference)
#include <cuda_runtime.h>

#define NXc 64
#define NYc 64
#define NSPOTS 64
#define Pc 6
#define TPB 256

__device__ __forceinline__ void red_add_f32(float* p, float v)
{
    asm volatile("red.global.add.f32 [%0], %1;" :: "l"(p), "f"(v) : "memory");
}

__global__ __launch_bounds__(TPB) void spot_render_kernel(
    const float* __restrict__ z, float* __restrict__ out)
{
    __shared__ float slx[NSPOTS * Pc];   // 500 * dx * valid
    __shared__ float sly[NSPOTS * Pc];   // 0.5 * dy * valid
    __shared__ int   smeta[NSPOTS];      // fbase(64*r0+c0) | valid<<13

    const int b    = blockIdx.x;
    const int tid  = threadIdx.x;
    const int lane = tid & 31;
    const int w    = tid >> 5;

    float* img = out + (size_t)b * (NXc * NYc);   // block-exclusive output region

    const float inv_alpha = 1.0f / (1.41421356237f * 0.92f);

    // ---- prologue: zero own gmem region (STG) + lambda/meta, ONE sync ----
    {
        float4* o4 = reinterpret_cast<float4*>(img);   // 1024 float4
        #pragma unroll
        for (int k = 0; k < 4; k++)
            o4[k * TPB + tid] = make_float4(0.f, 0.f, 0.f, 0.f);
    }
    {
        const int it = tid & 127;                // (s, d) item
        const int h  = tid >> 7;                 // half: j = 3h .. 3h+3
        const int s  = it & 63;
        const int d  = it >> 6;                  // 0 = x, 1 = y
        const float* zrow = z + (size_t)b * (2 * NSPOTS);
        const float x0 = __ldg(zrow + s);
        const float y0 = __ldg(zrow + NSPOTS + s);
        const int px = __float2int_rn(x0) - 3;   // round-half-even == jnp.round
        const int py = __float2int_rn(y0) - 3;
        const bool valid = (px >= 0) & (px < NXc - Pc) & (py >= 0) & (py < NYc - Pc);

        if ((d | h) == 0) {
            const int fbase = valid ? (64 * px + py) : 0;
            smeta[s] = fbase | ((int)valid << 13);
        }

        const float t0 = d ? (y0 - (float)py) : (x0 - (float)px);
        const float scale = (d ? 0.5f : 500.0f) * (valid ? 1.0f : 0.0f);
        const int jb = h * 3;
        const float e0 = erff(((float)(jb + 0) - 0.5f - t0) * inv_alpha);
        const float e1 = erff(((float)(jb + 1) - 0.5f - t0) * inv_alpha);
        const float e2 = erff(((float)(jb + 2) - 0.5f - t0) * inv_alpha);
        const float e3 = erff(((float)(jb + 3) - 0.5f - t0) * inv_alpha);
        float* dst = (d ? sly : slx) + s * Pc + jb;
        dst[0] = (e1 - e0) * scale;
        dst[1] = (e2 - e1) * scale;
        dst[2] = (e3 - e2) * scale;
    }
    __syncthreads();   // orders zero-STGs before REDs (cta fence) + publishes lambdas

    // ---- phase C: 8 spots per warp, fire-and-forget global REDG ----
    // pixel p = 6*ix + iy -> flat offset = 64*ix + iy = p + 58*ix (per-lane const)
    const int p    = lane;
    const int ix   = (p * 171) >> 10;            // p/6 for p <= 35
    const int iy   = p - ix * Pc;
    const int loff = p + 58 * ix;
    #pragma unroll
    for (int k = 0; k < 8; k++) {
        const int s    = w * 8 + k;
        const int meta = smeta[s];               // broadcast
        if (meta >> 13) {                        // warp-uniform: skip invalid spots
            const float v = slx[s * Pc + ix] * sly[s * Pc + iy];
            red_add_f32(&img[(meta & 8191) + loff], v);
        }
    }
    // batched residuals: pixels 32..35 (ix=5, iy=2..5) of 8 spots in ONE wavefront
    {
        const int s2   = w * 8 + (lane >> 2);
        const int meta = smeta[s2];
        if (meta >> 13) {                        // per-lane predicate
            const int iy2 = 2 + (lane & 3);
            const float v = slx[s2 * Pc + 5] * sly[s2 * Pc + iy2];
            red_add_f32(&img[(meta & 8191) + 320 + iy2], v);
        }
    }
}

extern "C" void kernel_launch(void* const* d_in, const int* in_sizes, int n_in,
                              void* d_out, int out_size)
{
    const float* z = (const float*)d_in[0];
    float* out = (float*)d_out;
    const int B = in_sizes[0] / (2 * NSPOTS);   // 8192
    spot_render_kernel<<<B, TPB>>>(z, out);
}

// round 15
// speedup vs baseline: 1.1043x; 1.1043x over previous
#include <cuda_runtime.h>

#define NXc 64
#define NYc 64
#define NSPOTS 64
#define Pc 6
#define TPB 256
#define RS  70                  // shared image row stride (70 mod 32 = 6; RS-6 = 64 -> bank = base+p)
#define IMG_FLOATS (NXc * RS)   // 4480

// Abramowitz-Stegun 7.1.26: |err| <= 1.5e-7 abs, branch-free
__device__ __forceinline__ float erf_as(float x)
{
    const float ax = fabsf(x);
    const float t  = __fdividef(1.0f, fmaf(0.3275911f, ax, 1.0f));
    float p = fmaf(1.061405429f, t, -1.453152027f);
    p = fmaf(p, t,  1.421413741f);
    p = fmaf(p, t, -0.284496736f);
    p = fmaf(p, t,  0.254829592f);
    p *= t;
    const float e = __expf(-ax * ax);
    const float r = fmaf(-p, e, 1.0f);
    return copysignf(r, x);
}

__global__ __launch_bounds__(TPB) void spot_render_kernel(
    const float* __restrict__ z, float* __restrict__ out)
{
    __shared__ float img[IMG_FLOATS];    // 17.5 KB, stride-70 rows
    __shared__ float slx[NSPOTS * Pc];   // 500 * dx * valid
    __shared__ float sly[NSPOTS * Pc];   // 0.5 * dy * valid
    __shared__ int   smeta[NSPOTS];      // base(70*r0+c0) | valid<<13

    const int b    = blockIdx.x;
    const int tid  = threadIdx.x;
    const int lane = tid & 31;
    const int w    = tid >> 5;

    const float inv_alpha = 1.0f / (1.41421356237f * 0.92f);

    // ---- balanced prologue, ONE sync: zero chunk + one erf half-item per thread ----
    {
        float4* im4 = reinterpret_cast<float4*>(img);    // 1120 float4
        #pragma unroll
        for (int k = 0; k < 4; k++)
            im4[k * TPB + tid] = make_float4(0.f, 0.f, 0.f, 0.f);
        if (tid < IMG_FLOATS / 4 - 4 * TPB)              // 96 extras
            im4[4 * TPB + tid] = make_float4(0.f, 0.f, 0.f, 0.f);
    }
    {
        const int it = tid & 127;                // (s, d) item
        const int h  = tid >> 7;                 // half: j = 3h .. 3h+3
        const int s  = it & 63;
        const int d  = it >> 6;                  // 0 = x, 1 = y
        const float* zrow = z + (size_t)b * (2 * NSPOTS);
        const float x0 = __ldg(zrow + s);
        const float y0 = __ldg(zrow + NSPOTS + s);
        const int px = __float2int_rn(x0) - 3;   // round-half-even == jnp.round
        const int py = __float2int_rn(y0) - 3;
        const bool valid = (px >= 0) & (px < NXc - Pc) & (py >= 0) & (py < NYc - Pc);

        if ((d | h) == 0) {
            const int base = valid ? (RS * px + py) : 0;
            smeta[s] = base | ((int)valid << 13);
        }

        const float t0 = d ? (y0 - (float)py) : (x0 - (float)px);
        const float scale = (d ? 0.5f : 500.0f) * (valid ? 1.0f : 0.0f);
        const int jb = h * 3;
        const float e0 = erf_as(((float)(jb + 0) - 0.5f - t0) * inv_alpha);
        const float e1 = erf_as(((float)(jb + 1) - 0.5f - t0) * inv_alpha);
        const float e2 = erf_as(((float)(jb + 2) - 0.5f - t0) * inv_alpha);
        const float e3 = erf_as(((float)(jb + 3) - 0.5f - t0) * inv_alpha);
        float* dst = (d ? sly : slx) + s * Pc + jb;
        dst[0] = (e1 - e0) * scale;
        dst[1] = (e2 - e1) * scale;
        dst[2] = (e3 - e2) * scale;
    }
    __syncthreads();

    // ---- phase C: 8 spots per warp; addr = base + (p + 64*ix), bank=(base+p)%32 ----
    const int p    = lane;
    const int ix   = (p * 171) >> 10;            // p/6 for p <= 35
    const int iy   = p - ix * Pc;
    const int loff = p + 64 * ix;                // per-lane constant offset
    #pragma unroll
    for (int k = 0; k < 8; k++) {
        const int s    = w * 8 + k;
        const int meta = smeta[s];               // broadcast
        if (meta >> 13) {                        // warp-uniform: skip invalid spots
            const float v = slx[s * Pc + ix] * sly[s * Pc + iy];
            atomicAdd(&img[(meta & 8191) + loff], v);
        }
    }
    // batched residuals: pixels 32..35 (ix=5, iy=2..5) of 8 spots in ONE atomic
    {
        const int s2   = w * 8 + (lane >> 2);
        const int meta = smeta[s2];
        if (meta >> 13) {
            const float v = slx[s2 * Pc + 5] * sly[s2 * Pc + 2 + (lane & 3)];
            atomicAdd(&img[(meta & 8191) + 352 + (lane & 3)], v);
        }
    }
    __syncthreads();

    // ---- phase D: linear LDS.64 + coalesced float2 STG ----
    float2* o2 = reinterpret_cast<float2*>(out + (size_t)b * (NXc * NYc));
    #pragma unroll
    for (int k = 0; k < 8; k++) {
        const int i  = k * TPB + tid;            // float2 cell 0..2047
        const int r  = i >> 5;                   // warp-uniform
        const int c2 = i & 31;
        o2[i] = *reinterpret_cast<const float2*>(&img[RS * r + 2 * c2]);
    }
}

extern "C" void kernel_launch(void* const* d_in, const int* in_sizes, int n_in,
                              void* d_out, int out_size)
{
    const float* z = (const float*)d_in[0];
    float* out = (float*)d_out;
    const int B = in_sizes[0] / (2 * NSPOTS);   // 8192
    spot_render_kernel<<<B, TPB>>>(z, out);
}